// round 1
// baseline (speedup 1.0000x reference)
#include <cuda_runtime.h>
#include <math.h>

#define NB   2
#define NS   2048
#define NHID 2048
#define NH   8
#define NKV  2
#define ND   256
#define NSW  512

typedef unsigned long long u64;

__device__ __forceinline__ float2 ffma2(float2 c, float2 a, float2 b) {
    u64 uc = *reinterpret_cast<u64*>(&c);
    u64 ua = *reinterpret_cast<u64*>(&a);
    u64 ub = *reinterpret_cast<u64*>(&b);
    asm("fma.rn.f32x2 %0, %1, %2, %0;" : "+l"(uc) : "l"(ua), "l"(ub));
    float2 r;
    *reinterpret_cast<u64*>(&r) = uc;
    return r;
}

// ---------------- scratch (no allocation allowed) ----------------
__device__ float g_qp [(size_t)NB*NS*NH*ND];   // [B,S,H,D]  q proj
__device__ float g_kp [(size_t)NB*NS*NKV*ND];  // [B,S,KV,D] k proj
__device__ float g_vp [(size_t)NB*NS*NKV*ND];  // [B,S,KV,D] v proj
__device__ float g_Q  [(size_t)NB*NH*NS*ND];   // [B,H,S,D]  rope+LN, *16
__device__ float g_K  [(size_t)NB*NKV*NS*ND];  // [B,KV,S,D]
__device__ float g_V  [(size_t)NB*NKV*NS*ND];  // [B,KV,S,D]
__device__ float g_Pf [(size_t)NB*NKV*NS*ND];  // inclusive prefix sum of g_V over S
__device__ float g_att[(size_t)NB*NS*NH*ND];   // [B,S,H*D] attention out

// ---------------- GEMM: C[m,n] = sum_k A[m,k]*B[n,k] (both K-major) ------
#define BM 128
#define BN 64
#define BKK 16

__global__ __launch_bounds__(256) void sgemm_nt(
    const float* __restrict__ A, const float* __restrict__ B,
    float* __restrict__ C, int M, int N, int K)
{
    __shared__ __align__(16) float As[BKK][BM + 4];   // stride 132 (16B-aligned rows)
    __shared__ __align__(16) float Bs[BKK][BN + 4];   // stride 68
    int tid = threadIdx.x;
    int tx = tid & 15, ty = tid >> 4;
    int bm = blockIdx.y * BM, bn = blockIdx.x * BN;
    const float* Ab = A + (size_t)bm * K;
    const float* Bb = B + (size_t)bn * K;
    int lr = tid >> 2;          // 0..63
    int lc = (tid & 3) << 2;    // 0,4,8,12

    float2 acc[8][2];
#pragma unroll
    for (int i = 0; i < 8; i++) { acc[i][0] = make_float2(0.f,0.f); acc[i][1] = make_float2(0.f,0.f); }

    for (int k0 = 0; k0 < K; k0 += BKK) {
        float4 a0 = *(const float4*)(Ab + (size_t)lr        * K + k0 + lc);
        float4 a1 = *(const float4*)(Ab + (size_t)(lr + 64) * K + k0 + lc);
        float4 b0 = *(const float4*)(Bb + (size_t)lr        * K + k0 + lc);
        __syncthreads();
        As[lc+0][lr] = a0.x; As[lc+1][lr] = a0.y; As[lc+2][lr] = a0.z; As[lc+3][lr] = a0.w;
        As[lc+0][lr+64] = a1.x; As[lc+1][lr+64] = a1.y; As[lc+2][lr+64] = a1.z; As[lc+3][lr+64] = a1.w;
        Bs[lc+0][lr] = b0.x; Bs[lc+1][lr] = b0.y; Bs[lc+2][lr] = b0.z; Bs[lc+3][lr] = b0.w;
        __syncthreads();
#pragma unroll
        for (int kk = 0; kk < BKK; kk++) {
            float4 bq  = *(const float4*)&Bs[kk][tx << 2];
            float2 b01 = make_float2(bq.x, bq.y);
            float2 b23 = make_float2(bq.z, bq.w);
            float4 aq0 = *(const float4*)&As[kk][ty << 3];
            float4 aq1 = *(const float4*)&As[kk][(ty << 3) + 4];
            float av[8] = {aq0.x,aq0.y,aq0.z,aq0.w,aq1.x,aq1.y,aq1.z,aq1.w};
#pragma unroll
            for (int i = 0; i < 8; i++) {
                float2 ai = make_float2(av[i], av[i]);
                acc[i][0] = ffma2(acc[i][0], ai, b01);
                acc[i][1] = ffma2(acc[i][1], ai, b23);
            }
        }
    }
#pragma unroll
    for (int i = 0; i < 8; i++) {
        float4 o = make_float4(acc[i][0].x, acc[i][0].y, acc[i][1].x, acc[i][1].y);
        *(float4*)(C + (size_t)(bm + (ty << 3) + i) * N + bn + (tx << 2)) = o;
    }
}

// ---------------- fused RoPE + unit-LayerNorm (+ q scale) ----------------
// blockIdx.x = b*S+s ; blockIdx.y = unit (0..7 q heads, 8..9 k heads, 10..11 v heads)
__global__ __launch_bounds__(256) void rope_ln_kernel(
    const float* __restrict__ qp, const float* __restrict__ kp, const float* __restrict__ vp,
    float* __restrict__ Qo, float* __restrict__ Ko, float* __restrict__ Vo)
{
    __shared__ float sh[ND];
    __shared__ float redA[8], redB[8];
    __shared__ float s_mu, s_inv;
    int bs = blockIdx.x;
    int s  = bs & (NS - 1);
    int b  = bs >> 11;
    int u  = blockIdx.y;
    int d  = threadIdx.x;

    const float* src; float* dst; bool doRope; float scale;
    if (u < NH) {
        src = qp + ((size_t)bs * NH + u) * ND;
        dst = Qo + (((size_t)(b * NH + u) * NS) + s) * ND;
        doRope = true; scale = 16.0f;               // 256 (query scalar) / 16 (1/sqrt(D))
    } else if (u < NH + NKV) {
        int h = u - NH;
        src = kp + ((size_t)bs * NKV + h) * ND;
        dst = Ko + (((size_t)(b * NKV + h) * NS) + s) * ND;
        doRope = true; scale = 1.0f;
    } else {
        int h = u - NH - NKV;
        src = vp + ((size_t)bs * NKV + h) * ND;
        dst = Vo + (((size_t)(b * NKV + h) * NS) + s) * ND;
        doRope = false; scale = 1.0f;
    }

    float x = src[d];
    float r = x;
    if (doRope) {
        sh[d] = x;
        __syncthreads();
        int j = d & 127;
        float invf = (float)(1.0 / pow(1.0e6, (double)j * (1.0 / 128.0)));
        float ang = (float)s * invf;
        float c = cosf(ang), sn = sinf(ang);
        float partner = (d < 128) ? -sh[d + 128] : sh[d - 128];
        r = x * c + partner * sn;
    }
    float s1 = r, s2 = r * r;
#pragma unroll
    for (int off = 16; off; off >>= 1) {
        s1 += __shfl_xor_sync(~0u, s1, off);
        s2 += __shfl_xor_sync(~0u, s2, off);
    }
    int w = d >> 5;
    if ((d & 31) == 0) { redA[w] = s1; redB[w] = s2; }
    __syncthreads();
    if (d == 0) {
        float A = 0.f, Bv = 0.f;
#pragma unroll
        for (int i = 0; i < 8; i++) { A += redA[i]; Bv += redB[i]; }
        float mu  = A * (1.0f / 256.0f);
        float var = Bv * (1.0f / 256.0f) - mu * mu;
        s_mu = mu; s_inv = rsqrtf(var + 1e-6f);
    }
    __syncthreads();
    dst[d] = (r - s_mu) * s_inv * scale;
}

// ---------------- inclusive prefix sum of V over S (for mask correction) ----
__global__ void vprefix_kernel(const float* __restrict__ V, float* __restrict__ P)
{
    int bh = blockIdx.x;
    int d  = threadIdx.x;
    const float* v = V + (size_t)bh * NS * ND + d;
    float*       p = P + (size_t)bh * NS * ND + d;
    float run = 0.f;
#pragma unroll 8
    for (int s = 0; s < NS; s++) {
        run += v[(size_t)s * ND];
        p[(size_t)s * ND] = run;
    }
}

// ---------------- sliding-window softcapped flash attention ----------------
#define AT_BM 64
#define AT_BN 64
#define QS_STR 260
#define KT_STR 68
#define VS_STR 260
#define PS_STR 68
#define ATT_SMEM ((16640 + 17408 + 16640 + 4352 + 256) * 4)   // 221184 B

__global__ __launch_bounds__(256, 1) void attn_kernel(
    const float* __restrict__ Q, const float* __restrict__ K,
    const float* __restrict__ V, const float* __restrict__ P,
    float* __restrict__ O)
{
    extern __shared__ __align__(16) float sm[];
    float* Qs    = sm;            // [64][260]
    float* Kt    = sm + 16640;    // [256][68]  (d-major)
    float* Vs    = sm + 34048;    // [64][260]
    float* Ps    = sm + 50688;    // [64][68]
    float* corrv = sm + 55040;    // [256]

    int tid = threadIdx.x;
    int tx = tid & 15, ty = tid >> 4;
    int qt = blockIdx.x, h = blockIdx.y, b = blockIdx.z;
    int qs = qt * AT_BM;
    int kvh = h >> 2;

    const float* Qb = Q + (((size_t)(b * NH  + h  ) * NS) + qs) * ND;
    const float* Kb = K + ((size_t)(b * NKV + kvh) * NS) * ND;
    const float* Vb = V + ((size_t)(b * NKV + kvh) * NS) * ND;
    const float* Pb = P + ((size_t)(b * NKV + kvh) * NS) * ND;

    int t0 = qs - (NSW - 1);
    int kstart = (t0 <= 0) ? 0 : (t0 & ~63);
    int kend = qs + AT_BM;
    float Ncf = (float)(NS - (kend - kstart));      // unprocessed (all masked) count

    // masked-v correction vector: V_total - V_range (all per-d)
    {
        float vt = Pb[(size_t)(NS - 1)   * ND + tid];
        float hi = Pb[(size_t)(kend - 1) * ND + tid];
        float lo = (kstart > 0) ? Pb[(size_t)(kstart - 1) * ND + tid] : 0.f;
        corrv[tid] = vt - hi + lo;
    }
    // load Q tile (row-major, padded)
#pragma unroll
    for (int it = 0; it < 16; it++) {
        int idx = tid + it * 256;
        int row = idx >> 6, c4 = idx & 63;
        float4 qv = *(const float4*)(Qb + (size_t)row * ND + (c4 << 2));
        float* q = Qs + row * QS_STR + (c4 << 2);
        q[0] = qv.x; q[1] = qv.y; q[2] = qv.z; q[3] = qv.w;
    }

    float2 acc[4][8];
#pragma unroll
    for (int i = 0; i < 4; i++)
#pragma unroll
        for (int c = 0; c < 8; c++) acc[i][c] = make_float2(0.f, 0.f);
    float Mrow[4], Lrow[4];
#pragma unroll
    for (int i = 0; i < 4; i++) { Mrow[i] = -3.0e38f; Lrow[i] = 0.f; }

    for (int k0 = kstart; k0 < kend; k0 += AT_BN) {
        __syncthreads();
        // load K (transposed to d-major) and V (row-major)
#pragma unroll
        for (int it = 0; it < 16; it++) {
            int idx = tid + it * 256;
            int row = idx >> 6, c4 = idx & 63;
            float4 kv = *(const float4*)(Kb + (size_t)(k0 + row) * ND + (c4 << 2));
            Kt[(c4 * 4 + 0) * KT_STR + row] = kv.x;
            Kt[(c4 * 4 + 1) * KT_STR + row] = kv.y;
            Kt[(c4 * 4 + 2) * KT_STR + row] = kv.z;
            Kt[(c4 * 4 + 3) * KT_STR + row] = kv.w;
            float4 vv = *(const float4*)(Vb + (size_t)(k0 + row) * ND + (c4 << 2));
            *(float4*)(Vs + row * VS_STR + (c4 << 2)) = vv;
        }
        __syncthreads();

        // scores: S[64x64] = Q . K^T   (q pre-scaled by 256/sqrt(D))
        float2 s2[4][2];
#pragma unroll
        for (int i = 0; i < 4; i++) { s2[i][0] = make_float2(0.f,0.f); s2[i][1] = make_float2(0.f,0.f); }
        const float* qrow = Qs + (ty << 2) * QS_STR;
#pragma unroll 8
        for (int d = 0; d < ND; d++) {
            float4 kq  = *(const float4*)(Kt + d * KT_STR + (tx << 2));
            float2 b01 = make_float2(kq.x, kq.y);
            float2 b23 = make_float2(kq.z, kq.w);
#pragma unroll
            for (int ii = 0; ii < 4; ii++) {
                float a = qrow[ii * QS_STR + d];
                float2 ap = make_float2(a, a);
                s2[ii][0] = ffma2(s2[ii][0], ap, b01);
                s2[ii][1] = ffma2(s2[ii][1], ap, b23);
            }
        }

        // softcap + mask + online softmax
#pragma unroll
        for (int ii = 0; ii < 4; ii++) {
            int gi = qs + (ty << 2) + ii;
            float sc[4] = { s2[ii][0].x, s2[ii][0].y, s2[ii][1].x, s2[ii][1].y };
            float rmax = -1e30f;
#pragma unroll
            for (int jj = 0; jj < 4; jj++) {
                int gj = k0 + (tx << 2) + jj;
                float v;
                if (gj <= gi && gj > gi - NSW)
                    v = 30.0f * tanhf(sc[jj] * (1.0f / 30.0f));
                else
                    v = -30.0f;                     // tanh(-inf/30)*30
                sc[jj] = v;
                rmax = fmaxf(rmax, v);
            }
#pragma unroll
            for (int off = 8; off; off >>= 1) rmax = fmaxf(rmax, __shfl_xor_sync(~0u, rmax, off));
            float Mnew = fmaxf(Mrow[ii], rmax);
            float f = expf(Mrow[ii] - Mnew);
            Mrow[ii] = Mnew;
            float rs = 0.f;
#pragma unroll
            for (int jj = 0; jj < 4; jj++) {
                float p = expf(sc[jj] - Mnew);
                Ps[((ty << 2) + ii) * PS_STR + (tx << 2) + jj] = p;
                rs += p;
            }
#pragma unroll
            for (int off = 8; off; off >>= 1) rs += __shfl_xor_sync(~0u, rs, off);
            Lrow[ii] = Lrow[ii] * f + rs;
#pragma unroll
            for (int cc = 0; cc < 8; cc++) { acc[ii][cc].x *= f; acc[ii][cc].y *= f; }
        }
        __syncthreads();

        // PV: out[64x256] += P[64x64] . V[64x256]
#pragma unroll 4
        for (int kk = 0; kk < AT_BN; kk++) {
            const float* vrow = Vs + kk * VS_STR + (tx << 4);
            float4 v0 = *(const float4*)(vrow);
            float4 v1 = *(const float4*)(vrow + 4);
            float4 v2 = *(const float4*)(vrow + 8);
            float4 v3 = *(const float4*)(vrow + 12);
            float2 vv[8] = {
                make_float2(v0.x,v0.y), make_float2(v0.z,v0.w),
                make_float2(v1.x,v1.y), make_float2(v1.z,v1.w),
                make_float2(v2.x,v2.y), make_float2(v2.z,v2.w),
                make_float2(v3.x,v3.y), make_float2(v3.z,v3.w)
            };
#pragma unroll
            for (int ii = 0; ii < 4; ii++) {
                float p = Ps[((ty << 2) + ii) * PS_STR + kk];
                float2 pp = make_float2(p, p);
#pragma unroll
                for (int cc = 0; cc < 8; cc++) acc[ii][cc] = ffma2(acc[ii][cc], pp, vv[cc]);
            }
        }
    }

    // epilogue: add masked-position mass exactly, normalize, store [B,S,H*D]
#pragma unroll
    for (int ii = 0; ii < 4; ii++) {
        float ce = expf(-30.0f - Mrow[ii]);
        float invL = 1.0f / (Lrow[ii] + ce * Ncf);
        int row = qs + (ty << 2) + ii;
        float* ob = O + (((size_t)(b * NS + row) * NH) + h) * ND + (tx << 4);
#pragma unroll
        for (int g = 0; g < 4; g++) {
            float2 a0 = acc[ii][g * 2], a1 = acc[ii][g * 2 + 1];
            int c0 = (tx << 4) + g * 4;
            float4 o;
            o.x = (a0.x + ce * corrv[c0 + 0]) * invL;
            o.y = (a0.y + ce * corrv[c0 + 1]) * invL;
            o.z = (a1.x + ce * corrv[c0 + 2]) * invL;
            o.w = (a1.y + ce * corrv[c0 + 3]) * invL;
            *(float4*)(ob + g * 4) = o;
        }
    }
}

// ---------------- launch ----------------
extern "C" void kernel_launch(void* const* d_in, const int* in_sizes, int n_in,
                              void* d_out, int out_size)
{
    const float* hs = (const float*)d_in[0];
    const float* Wq = (const float*)d_in[1];
    const float* Wk = (const float*)d_in[2];
    const float* Wv = (const float*)d_in[3];
    const float* Wo = (const float*)d_in[4];
    float* out = (float*)d_out;

    float *qp, *kp, *vp, *Qn, *Kn, *Vn, *Pf, *att;
    cudaGetSymbolAddress((void**)&qp,  g_qp);
    cudaGetSymbolAddress((void**)&kp,  g_kp);
    cudaGetSymbolAddress((void**)&vp,  g_vp);
    cudaGetSymbolAddress((void**)&Qn,  g_Q);
    cudaGetSymbolAddress((void**)&Kn,  g_K);
    cudaGetSymbolAddress((void**)&Vn,  g_V);
    cudaGetSymbolAddress((void**)&Pf,  g_Pf);
    cudaGetSymbolAddress((void**)&att, g_att);

    const int M = NB * NS;   // 4096

    // projections
    sgemm_nt<<<dim3(NHID / BN, M / BM), 256>>>(hs, Wq, qp, M, NH * ND, NHID);
    sgemm_nt<<<dim3((NKV * ND) / BN, M / BM), 256>>>(hs, Wk, kp, M, NKV * ND, NHID);
    sgemm_nt<<<dim3((NKV * ND) / BN, M / BM), 256>>>(hs, Wv, vp, M, NKV * ND, NHID);

    // rope + per-head layernorm (+ query scaling folded)
    rope_ln_kernel<<<dim3(NB * NS, NH + 2 * NKV), 256>>>(qp, kp, vp, Qn, Kn, Vn);

    // prefix sums of normalized V (exact masked-softmax correction)
    vprefix_kernel<<<NB * NKV, 256>>>(Vn, Pf);

    // attention
    cudaFuncSetAttribute(attn_kernel, cudaFuncAttributeMaxDynamicSharedMemorySize, ATT_SMEM);
    attn_kernel<<<dim3(NS / AT_BM, NH, NB), 256, ATT_SMEM>>>(Qn, Kn, Vn, Pf, att);

    // output projection
    sgemm_nt<<<dim3(NHID / BN, M / BM), 256>>>(att, Wo, out, M, NHID, NHID);
}

// round 3
// speedup vs baseline: 1.3064x; 1.3064x over previous
#include <cuda_runtime.h>
#include <cuda_bf16.h>
#include <math.h>

#define NB   2
#define NS   2048
#define NHID 2048
#define NH   8
#define NKV  2
#define ND   256
#define NSW  512

typedef unsigned long long u64;
typedef unsigned int u32;

__device__ __forceinline__ float2 ffma2(float2 c, float2 a, float2 b) {
    u64 uc = *reinterpret_cast<u64*>(&c);
    u64 ua = *reinterpret_cast<u64*>(&a);
    u64 ub = *reinterpret_cast<u64*>(&b);
    asm("fma.rn.f32x2 %0, %1, %2, %0;" : "+l"(uc) : "l"(ua), "l"(ub));
    float2 r;
    *reinterpret_cast<u64*>(&r) = uc;
    return r;
}

__device__ __forceinline__ u32 smem_u32(const void* p) {
    u32 a;
    asm("{ .reg .u64 t; cvta.to.shared.u64 t, %1; cvt.u32.u64 %0, t; }" : "=r"(a) : "l"(p));
    return a;
}

#define SWZ(o) ((o) ^ (((o) >> 3) & 0x70))

#define CP_ASYNC16(saddr, gptr) \
    asm volatile("cp.async.ca.shared.global [%0], [%1], 16;" :: "r"(saddr), "l"(gptr) : "memory")
#define CP_COMMIT() asm volatile("cp.async.commit_group;" ::: "memory")
#define CP_WAIT2()  asm volatile("cp.async.wait_group 2;" ::: "memory")
#define CP_WAIT0()  asm volatile("cp.async.wait_group 0;" ::: "memory")

#define LDMX4(r0, r1, r2, r3, addr) \
    asm volatile("ldmatrix.sync.aligned.m8n8.x4.shared.b16 {%0,%1,%2,%3}, [%4];" \
        : "=r"(r0), "=r"(r1), "=r"(r2), "=r"(r3) : "r"(addr))

#define MMA16816(d0, d1, d2, d3, a0, a1, a2, a3, b0, b1) \
    asm volatile("mma.sync.aligned.m16n8k16.row.col.f32.bf16.bf16.f32 " \
        "{%0,%1,%2,%3}, {%4,%5,%6,%7}, {%8,%9}, {%0,%1,%2,%3};" \
        : "+f"(d0), "+f"(d1), "+f"(d2), "+f"(d3) \
        : "r"(a0), "r"(a1), "r"(a2), "r"(a3), "r"(b0), "r"(b1))

// ---------------- scratch ----------------
__device__ float g_qp [(size_t)NB*NS*NH*ND];
__device__ float g_kp [(size_t)NB*NS*NKV*ND];
__device__ float g_vp [(size_t)NB*NS*NKV*ND];
__device__ float g_Q  [(size_t)NB*NH*NS*ND];
__device__ float g_K  [(size_t)NB*NKV*NS*ND];
__device__ float g_V  [(size_t)NB*NKV*NS*ND];
__device__ float g_bs [(size_t)NB*NKV*(NS/64)*ND];
__device__ float g_att[(size_t)NB*NS*NH*ND];

__device__ __nv_bfloat16 g_hsh[(size_t)NB*NS*NHID], g_hsl[(size_t)NB*NS*NHID];
__device__ __nv_bfloat16 g_wqh[(size_t)NH*ND*NHID], g_wql[(size_t)NH*ND*NHID];
__device__ __nv_bfloat16 g_wkh[(size_t)NKV*ND*NHID], g_wkl[(size_t)NKV*ND*NHID];
__device__ __nv_bfloat16 g_wvh[(size_t)NKV*ND*NHID], g_wvl[(size_t)NKV*ND*NHID];
__device__ __nv_bfloat16 g_woh[(size_t)NHID*NHID], g_wol[(size_t)NHID*NHID];
__device__ __nv_bfloat16 g_ath[(size_t)NB*NS*NH*ND], g_atl[(size_t)NB*NS*NH*ND];

// ---------------- fp32 -> bf16 hi/lo split ----------------
__global__ __launch_bounds__(256) void cvt_split(
    const float* __restrict__ x, __nv_bfloat16* __restrict__ hi,
    __nv_bfloat16* __restrict__ lo, int n4)
{
    int i = blockIdx.x * 256 + threadIdx.x;
    if (i >= n4) return;
    float4 v = *(const float4*)(x + (size_t)i * 4);
    __nv_bfloat16 h0 = __float2bfloat16(v.x);
    __nv_bfloat16 h1 = __float2bfloat16(v.y);
    __nv_bfloat16 h2 = __float2bfloat16(v.z);
    __nv_bfloat16 h3 = __float2bfloat16(v.w);
    __nv_bfloat16 l0 = __float2bfloat16(v.x - __bfloat162float(h0));
    __nv_bfloat16 l1 = __float2bfloat16(v.y - __bfloat162float(h1));
    __nv_bfloat16 l2 = __float2bfloat16(v.z - __bfloat162float(h2));
    __nv_bfloat16 l3 = __float2bfloat16(v.w - __bfloat162float(h3));
    ushort4 H, L;
    H.x = __bfloat16_as_ushort(h0); H.y = __bfloat16_as_ushort(h1);
    H.z = __bfloat16_as_ushort(h2); H.w = __bfloat16_as_ushort(h3);
    L.x = __bfloat16_as_ushort(l0); L.y = __bfloat16_as_ushort(l1);
    L.z = __bfloat16_as_ushort(l2); L.w = __bfloat16_as_ushort(l3);
    *(ushort4*)(hi + (size_t)i * 4) = H;
    *(ushort4*)(lo + (size_t)i * 4) = L;
}

// ---------------- HMMA split-bf16 GEMM ----------------
// C[m,n] = sum_k A[m,k]*B[n,k]  via Ah*Bh + Ah*Bl + Al*Bh
// block tile 128x128, 8 warps (warptile 64x32), K-chunk 64, 3-stage cp.async
#define GS_STAGE 65536
#define GS_AH 0
#define GS_AL 16384
#define GS_BH 32768
#define GS_BL 49152
#define GS_TOTAL (3 * GS_STAGE)

__global__ __launch_bounds__(256, 1) void gemm_mma(
    const __nv_bfloat16* __restrict__ Ah, const __nv_bfloat16* __restrict__ Al,
    const __nv_bfloat16* __restrict__ Bh, const __nv_bfloat16* __restrict__ Bl,
    float* __restrict__ C, int M, int N, int K)
{
    extern __shared__ char sm[];
    u32 sb = smem_u32(sm);
    int tid = threadIdx.x;
    int lane = tid & 31, wid = tid >> 5;
    int warpM = wid >> 2, warpN = wid & 3;
    int bm = blockIdx.y * 128, bn = blockIdx.x * 128;

    const int nIt = K >> 6;   // 32

    float d[4][4][4];
#pragma unroll
    for (int i = 0; i < 4; i++)
#pragma unroll
        for (int j = 0; j < 4; j++)
#pragma unroll
            for (int c = 0; c < 4; c++) d[i][j][c] = 0.f;

    // per-thread load coords: 4 chunks of 16B per tile
    int q0 = tid;            // chunk ids q0 + 256*i, row=q>>3, cb=q&7

    // prologue: stages 0,1
#pragma unroll
    for (int pit = 0; pit < 2; pit++) {
        u32 stg = sb + pit * GS_STAGE;
        int k0 = pit << 6;
#pragma unroll
        for (int i = 0; i < 4; i++) {
            int q = q0 + i * 256;
            int row = q >> 3, cb = q & 7;
            u32 doff = SWZ((u32)(row * 128 + cb * 16));
            size_t ga = (size_t)(bm + row) * K + k0 + cb * 8;
            size_t gb = (size_t)(bn + row) * K + k0 + cb * 8;
            CP_ASYNC16(stg + GS_AH + doff, Ah + ga);
            CP_ASYNC16(stg + GS_AL + doff, Al + ga);
            CP_ASYNC16(stg + GS_BH + doff, Bh + gb);
            CP_ASYNC16(stg + GS_BL + doff, Bl + gb);
        }
        CP_COMMIT();
    }

    for (int it = 0; it < nIt; it++) {
        __syncthreads();
        if (it + 2 < nIt) {
            u32 stg = sb + ((it + 2) % 3) * GS_STAGE;
            int k0 = (it + 2) << 6;
#pragma unroll
            for (int i = 0; i < 4; i++) {
                int q = q0 + i * 256;
                int row = q >> 3, cb = q & 7;
                u32 doff = SWZ((u32)(row * 128 + cb * 16));
                size_t ga = (size_t)(bm + row) * K + k0 + cb * 8;
                size_t gb = (size_t)(bn + row) * K + k0 + cb * 8;
                CP_ASYNC16(stg + GS_AH + doff, Ah + ga);
                CP_ASYNC16(stg + GS_AL + doff, Al + ga);
                CP_ASYNC16(stg + GS_BH + doff, Bh + gb);
                CP_ASYNC16(stg + GS_BL + doff, Bl + gb);
            }
        }
        CP_COMMIT();
        CP_WAIT2();
        __syncthreads();

        u32 stg = sb + (it % 3) * GS_STAGE;
#pragma unroll
        for (int kk = 0; kk < 4; kk++) {
            u32 ah[4][4], al[4][4];
#pragma unroll
            for (int i = 0; i < 4; i++) {
                int row = warpM * 64 + i * 16 + (lane & 15);
                u32 colb = kk * 32 + ((lane >> 4) << 4);
                u32 off = SWZ((u32)(row * 128 + colb));
                LDMX4(ah[i][0], ah[i][1], ah[i][2], ah[i][3], stg + GS_AH + off);
                LDMX4(al[i][0], al[i][1], al[i][2], al[i][3], stg + GS_AL + off);
            }
            u32 bh[2][4], bl[2][4];
#pragma unroll
            for (int p = 0; p < 2; p++) {
                int row = warpN * 32 + p * 16 + (lane & 7) + ((lane >> 4) << 3);
                u32 colb = kk * 32 + (((lane >> 3) & 1) << 4);
                u32 off = SWZ((u32)(row * 128 + colb));
                LDMX4(bh[p][0], bh[p][1], bh[p][2], bh[p][3], stg + GS_BH + off);
                LDMX4(bl[p][0], bl[p][1], bl[p][2], bl[p][3], stg + GS_BL + off);
            }
#pragma unroll
            for (int i = 0; i < 4; i++) {
#pragma unroll
                for (int j = 0; j < 4; j++) {
                    int p = j >> 1, h2 = (j & 1) << 1;
                    MMA16816(d[i][j][0], d[i][j][1], d[i][j][2], d[i][j][3],
                             ah[i][0], ah[i][1], ah[i][2], ah[i][3],
                             bh[p][h2], bh[p][h2 + 1]);
                    MMA16816(d[i][j][0], d[i][j][1], d[i][j][2], d[i][j][3],
                             ah[i][0], ah[i][1], ah[i][2], ah[i][3],
                             bl[p][h2], bl[p][h2 + 1]);
                    MMA16816(d[i][j][0], d[i][j][1], d[i][j][2], d[i][j][3],
                             al[i][0], al[i][1], al[i][2], al[i][3],
                             bh[p][h2], bh[p][h2 + 1]);
                }
            }
        }
    }
    CP_WAIT0();

    // epilogue
#pragma unroll
    for (int i = 0; i < 4; i++) {
#pragma unroll
        for (int j = 0; j < 4; j++) {
            int r0 = bm + warpM * 64 + i * 16 + (lane >> 2);
            int cc = bn + warpN * 32 + j * 8 + (lane & 3) * 2;
            float2 v0 = make_float2(d[i][j][0], d[i][j][1]);
            float2 v1 = make_float2(d[i][j][2], d[i][j][3]);
            *(float2*)(C + (size_t)r0 * N + cc) = v0;
            *(float2*)(C + (size_t)(r0 + 8) * N + cc) = v1;
        }
    }
}

// ---------------- fused RoPE + unit-LayerNorm (+ q scale) ----------------
__global__ __launch_bounds__(256) void rope_ln_kernel(
    const float* __restrict__ qp, const float* __restrict__ kp, const float* __restrict__ vp,
    float* __restrict__ Qo, float* __restrict__ Ko, float* __restrict__ Vo)
{
    __shared__ float sh[ND];
    __shared__ float redA[8], redB[8];
    __shared__ float s_mu, s_inv;
    int bs = blockIdx.x;
    int s  = bs & (NS - 1);
    int b  = bs >> 11;
    int u  = blockIdx.y;
    int d  = threadIdx.x;

    const float* src; float* dst; bool doRope; float scale;
    if (u < NH) {
        src = qp + ((size_t)bs * NH + u) * ND;
        dst = Qo + (((size_t)(b * NH + u) * NS) + s) * ND;
        doRope = true; scale = 16.0f;
    } else if (u < NH + NKV) {
        int h = u - NH;
        src = kp + ((size_t)bs * NKV + h) * ND;
        dst = Ko + (((size_t)(b * NKV + h) * NS) + s) * ND;
        doRope = true; scale = 1.0f;
    } else {
        int h = u - NH - NKV;
        src = vp + ((size_t)bs * NKV + h) * ND;
        dst = Vo + (((size_t)(b * NKV + h) * NS) + s) * ND;
        doRope = false; scale = 1.0f;
    }

    float x = src[d];
    float r = x;
    if (doRope) {
        sh[d] = x;
        __syncthreads();
        int j = d & 127;
        float invf = (float)(1.0 / pow(1.0e6, (double)j * (1.0 / 128.0)));
        float ang = (float)s * invf;
        float c = cosf(ang), sn = sinf(ang);
        float partner = (d < 128) ? -sh[d + 128] : sh[d - 128];
        r = x * c + partner * sn;
    }
    float s1 = r, s2 = r * r;
#pragma unroll
    for (int off = 16; off; off >>= 1) {
        s1 += __shfl_xor_sync(~0u, s1, off);
        s2 += __shfl_xor_sync(~0u, s2, off);
    }
    int w = d >> 5;
    if ((d & 31) == 0) { redA[w] = s1; redB[w] = s2; }
    __syncthreads();
    if (d == 0) {
        float A = 0.f, Bv = 0.f;
#pragma unroll
        for (int i = 0; i < 8; i++) { A += redA[i]; Bv += redB[i]; }
        float mu  = A * (1.0f / 256.0f);
        float var = Bv * (1.0f / 256.0f) - mu * mu;
        s_mu = mu; s_inv = rsqrtf(var + 1e-6f);
    }
    __syncthreads();
    dst[d] = (r - s_mu) * s_inv * scale;
}

// ---------------- 64-row block sums of V (mask-correction) ----------------
__global__ __launch_bounds__(256) void vblocksum_kernel(
    const float* __restrict__ V, float* __restrict__ BSo)
{
    int bh = blockIdx.x, blk = blockIdx.y, d = threadIdx.x;
    const float* v = V + ((size_t)bh * NS + blk * 64) * ND + d;
    float s = 0.f;
#pragma unroll 8
    for (int i = 0; i < 64; i++) s += v[(size_t)i * ND];
    BSo[((size_t)bh * (NS / 64) + blk) * ND + d] = s;
}

// ---------------- sliding-window softcapped flash attention ----------------
#define AT_BM 64
#define AT_BN 64
#define QS_STR 260
#define KT_STR 68
#define VS_STR 260
#define PS_STR 68
#define ATT_SMEM ((16640 + 17408 + 16640 + 4352 + 256) * 4)

__global__ __launch_bounds__(256, 1) void attn_kernel(
    const float* __restrict__ Q, const float* __restrict__ K,
    const float* __restrict__ V, const float* __restrict__ BS,
    float* __restrict__ O)
{
    extern __shared__ __align__(16) float smf[];
    float* Qs    = smf;
    float* Kt    = smf + 16640;
    float* Vs    = smf + 34048;
    float* Ps    = smf + 50688;
    float* corrv = smf + 55040;

    int tid = threadIdx.x;
    int tx = tid & 15, ty = tid >> 4;
    int qt = blockIdx.x, h = blockIdx.y, b = blockIdx.z;
    int qs = qt * AT_BM;
    int kvh = h >> 2;

    const float* Qb = Q + (((size_t)(b * NH  + h  ) * NS) + qs) * ND;
    const float* Kb = K + ((size_t)(b * NKV + kvh) * NS) * ND;
    const float* Vb = V + ((size_t)(b * NKV + kvh) * NS) * ND;
    const float* Bb = BS + (size_t)(b * NKV + kvh) * (NS / 64) * ND;

    int t0 = qs - (NSW - 1);
    int kstart = (t0 <= 0) ? 0 : (t0 & ~63);
    int kend = qs + AT_BM;
    float Ncf = (float)(NS - (kend - kstart));
    int bs0 = kstart >> 6, bs1 = kend >> 6;

    {
        float c = 0.f;
#pragma unroll
        for (int blk = 0; blk < NS / 64; blk++) {
            float x = Bb[(size_t)blk * ND + tid];
            if (blk < bs0 || blk >= bs1) c += x;
        }
        corrv[tid] = c;
    }
#pragma unroll
    for (int it = 0; it < 16; it++) {
        int idx = tid + it * 256;
        int row = idx >> 6, c4 = idx & 63;
        float4 qv = *(const float4*)(Qb + (size_t)row * ND + (c4 << 2));
        float* q = Qs + row * QS_STR + (c4 << 2);
        q[0] = qv.x; q[1] = qv.y; q[2] = qv.z; q[3] = qv.w;
    }

    float2 acc[4][8];
#pragma unroll
    for (int i = 0; i < 4; i++)
#pragma unroll
        for (int c = 0; c < 8; c++) acc[i][c] = make_float2(0.f, 0.f);
    float Mrow[4], Lrow[4];
#pragma unroll
    for (int i = 0; i < 4; i++) { Mrow[i] = -3.0e38f; Lrow[i] = 0.f; }

    for (int k0 = kstart; k0 < kend; k0 += AT_BN) {
        __syncthreads();
#pragma unroll
        for (int it = 0; it < 16; it++) {
            int idx = tid + it * 256;
            int row = idx >> 6, c4 = idx & 63;
            float4 kv = *(const float4*)(Kb + (size_t)(k0 + row) * ND + (c4 << 2));
            Kt[(c4 * 4 + 0) * KT_STR + row] = kv.x;
            Kt[(c4 * 4 + 1) * KT_STR + row] = kv.y;
            Kt[(c4 * 4 + 2) * KT_STR + row] = kv.z;
            Kt[(c4 * 4 + 3) * KT_STR + row] = kv.w;
            float4 vv = *(const float4*)(Vb + (size_t)(k0 + row) * ND + (c4 << 2));
            *(float4*)(Vs + row * VS_STR + (c4 << 2)) = vv;
        }
        __syncthreads();

        float2 s2[4][2];
#pragma unroll
        for (int i = 0; i < 4; i++) { s2[i][0] = make_float2(0.f,0.f); s2[i][1] = make_float2(0.f,0.f); }
        const float* qrow = Qs + (ty << 2) * QS_STR;
#pragma unroll 8
        for (int d = 0; d < ND; d++) {
            float4 kq  = *(const float4*)(Kt + d * KT_STR + (tx << 2));
            float2 b01 = make_float2(kq.x, kq.y);
            float2 b23 = make_float2(kq.z, kq.w);
#pragma unroll
            for (int ii = 0; ii < 4; ii++) {
                float a = qrow[ii * QS_STR + d];
                float2 ap = make_float2(a, a);
                s2[ii][0] = ffma2(s2[ii][0], ap, b01);
                s2[ii][1] = ffma2(s2[ii][1], ap, b23);
            }
        }

#pragma unroll
        for (int ii = 0; ii < 4; ii++) {
            int gi = qs + (ty << 2) + ii;
            float sc[4] = { s2[ii][0].x, s2[ii][0].y, s2[ii][1].x, s2[ii][1].y };
            float rmax = -1e30f;
#pragma unroll
            for (int jj = 0; jj < 4; jj++) {
                int gj = k0 + (tx << 2) + jj;
                float v;
                if (gj <= gi && gj > gi - NSW)
                    v = 30.0f * tanhf(sc[jj] * (1.0f / 30.0f));
                else
                    v = -30.0f;
                sc[jj] = v;
                rmax = fmaxf(rmax, v);
            }
#pragma unroll
            for (int off = 8; off; off >>= 1) rmax = fmaxf(rmax, __shfl_xor_sync(~0u, rmax, off));
            float Mnew = fmaxf(Mrow[ii], rmax);
            float f = expf(Mrow[ii] - Mnew);
            Mrow[ii] = Mnew;
            float rs = 0.f;
#pragma unroll
            for (int jj = 0; jj < 4; jj++) {
                float p = expf(sc[jj] - Mnew);
                Ps[((ty << 2) + ii) * PS_STR + (tx << 2) + jj] = p;
                rs += p;
            }
#pragma unroll
            for (int off = 8; off; off >>= 1) rs += __shfl_xor_sync(~0u, rs, off);
            Lrow[ii] = Lrow[ii] * f + rs;
#pragma unroll
            for (int cc = 0; cc < 8; cc++) { acc[ii][cc].x *= f; acc[ii][cc].y *= f; }
        }
        __syncthreads();

#pragma unroll 4
        for (int kk = 0; kk < AT_BN; kk++) {
            const float* vrow = Vs + kk * VS_STR + (tx << 4);
            float4 v0 = *(const float4*)(vrow);
            float4 v1 = *(const float4*)(vrow + 4);
            float4 v2 = *(const float4*)(vrow + 8);
            float4 v3 = *(const float4*)(vrow + 12);
            float2 vv[8] = {
                make_float2(v0.x,v0.y), make_float2(v0.z,v0.w),
                make_float2(v1.x,v1.y), make_float2(v1.z,v1.w),
                make_float2(v2.x,v2.y), make_float2(v2.z,v2.w),
                make_float2(v3.x,v3.y), make_float2(v3.z,v3.w)
            };
#pragma unroll
            for (int ii = 0; ii < 4; ii++) {
                float p = Ps[((ty << 2) + ii) * PS_STR + kk];
                float2 pp = make_float2(p, p);
#pragma unroll
                for (int cc = 0; cc < 8; cc++) acc[ii][cc] = ffma2(acc[ii][cc], pp, vv[cc]);
            }
        }
    }

#pragma unroll
    for (int ii = 0; ii < 4; ii++) {
        float ce = expf(-30.0f - Mrow[ii]);
        float invL = 1.0f / (Lrow[ii] + ce * Ncf);
        int row = qs + (ty << 2) + ii;
        float* ob = O + (((size_t)(b * NS + row) * NH) + h) * ND + (tx << 4);
#pragma unroll
        for (int g = 0; g < 4; g++) {
            float2 a0 = acc[ii][g * 2], a1 = acc[ii][g * 2 + 1];
            int c0 = (tx << 4) + g * 4;
            float4 o;
            o.x = (a0.x + ce * corrv[c0 + 0]) * invL;
            o.y = (a0.y + ce * corrv[c0 + 1]) * invL;
            o.z = (a1.x + ce * corrv[c0 + 2]) * invL;
            o.w = (a1.y + ce * corrv[c0 + 3]) * invL;
            *(float4*)(ob + g * 4) = o;
        }
    }
}

// ---------------- launch ----------------
extern "C" void kernel_launch(void* const* d_in, const int* in_sizes, int n_in,
                              void* d_out, int out_size)
{
    const float* hs = (const float*)d_in[0];
    const float* Wq = (const float*)d_in[1];
    const float* Wk = (const float*)d_in[2];
    const float* Wv = (const float*)d_in[3];
    const float* Wo = (const float*)d_in[4];
    float* out = (float*)d_out;

    float *qp, *kp, *vp, *Qn, *Kn, *Vn, *bs, *att;
    cudaGetSymbolAddress((void**)&qp,  g_qp);
    cudaGetSymbolAddress((void**)&kp,  g_kp);
    cudaGetSymbolAddress((void**)&vp,  g_vp);
    cudaGetSymbolAddress((void**)&Qn,  g_Q);
    cudaGetSymbolAddress((void**)&Kn,  g_K);
    cudaGetSymbolAddress((void**)&Vn,  g_V);
    cudaGetSymbolAddress((void**)&bs,  g_bs);
    cudaGetSymbolAddress((void**)&att, g_att);

    __nv_bfloat16 *hsh,*hsl,*wqh,*wql,*wkh,*wkl,*wvh,*wvl,*woh,*wol,*ath,*atl;
    cudaGetSymbolAddress((void**)&hsh, g_hsh); cudaGetSymbolAddress((void**)&hsl, g_hsl);
    cudaGetSymbolAddress((void**)&wqh, g_wqh); cudaGetSymbolAddress((void**)&wql, g_wql);
    cudaGetSymbolAddress((void**)&wkh, g_wkh); cudaGetSymbolAddress((void**)&wkl, g_wkl);
    cudaGetSymbolAddress((void**)&wvh, g_wvh); cudaGetSymbolAddress((void**)&wvl, g_wvl);
    cudaGetSymbolAddress((void**)&woh, g_woh); cudaGetSymbolAddress((void**)&wol, g_wol);
    cudaGetSymbolAddress((void**)&ath, g_ath); cudaGetSymbolAddress((void**)&atl, g_atl);

    const int M = NB * NS;   // 4096

    cudaFuncSetAttribute(gemm_mma, cudaFuncAttributeMaxDynamicSharedMemorySize, GS_TOTAL);
    cudaFuncSetAttribute(attn_kernel, cudaFuncAttributeMaxDynamicSharedMemorySize, ATT_SMEM);

    // split conversions
    {
        int n;
        n = M * NHID;            cvt_split<<<n/1024, 256>>>(hs, hsh, hsl, n/4);
        n = NH * ND * NHID;      cvt_split<<<n/1024, 256>>>(Wq, wqh, wql, n/4);
        n = NKV * ND * NHID;     cvt_split<<<n/1024, 256>>>(Wk, wkh, wkl, n/4);
        n = NKV * ND * NHID;     cvt_split<<<n/1024, 256>>>(Wv, wvh, wvl, n/4);
        n = NHID * NHID;         cvt_split<<<n/1024, 256>>>(Wo, woh, wol, n/4);
    }

    // projections on tensor cores (HMMA)
    gemm_mma<<<dim3((NH*ND)/128, M/128), 256, GS_TOTAL>>>(hsh, hsl, wqh, wql, qp, M, NH*ND, NHID);
    gemm_mma<<<dim3((NKV*ND)/128, M/128), 256, GS_TOTAL>>>(hsh, hsl, wkh, wkl, kp, M, NKV*ND, NHID);
    gemm_mma<<<dim3((NKV*ND)/128, M/128), 256, GS_TOTAL>>>(hsh, hsl, wvh, wvl, vp, M, NKV*ND, NHID);

    // rope + per-head layernorm (+ query scaling folded)
    rope_ln_kernel<<<dim3(NB * NS, NH + 2 * NKV), 256>>>(qp, kp, vp, Qn, Kn, Vn);

    // 64-row block sums of normalized V (exact masked-softmax correction)
    vblocksum_kernel<<<dim3(NB * NKV, NS / 64), 256>>>(Vn, bs);

    // attention
    attn_kernel<<<dim3(NS / AT_BM, NH, NB), 256, ATT_SMEM>>>(Qn, Kn, Vn, bs, att);

    // output projection
    {
        int n = M * NHID;
        cvt_split<<<n/1024, 256>>>(att, ath, atl, n/4);
    }
    gemm_mma<<<dim3(NHID/128, M/128), 256, GS_TOTAL>>>(ath, atl, woh, wol, out, M, NHID, NHID);
}

// round 4
// speedup vs baseline: 2.8974x; 2.2178x over previous
#include <cuda_runtime.h>
#include <cuda_fp16.h>
#include <math.h>

#define NB   2
#define NS   2048
#define NHID 2048
#define NH   8
#define NKV  2
#define ND   256
#define NSW  512
#define NQKV 3072   // 2048 q + 512 k + 512 v

typedef unsigned long long u64;
typedef unsigned int u32;

__device__ __forceinline__ float2 ffma2(float2 c, float2 a, float2 b) {
    u64 uc = *reinterpret_cast<u64*>(&c);
    u64 ua = *reinterpret_cast<u64*>(&a);
    u64 ub = *reinterpret_cast<u64*>(&b);
    asm("fma.rn.f32x2 %0, %1, %2, %0;" : "+l"(uc) : "l"(ua), "l"(ub));
    float2 r;
    *reinterpret_cast<u64*>(&r) = uc;
    return r;
}

__device__ __forceinline__ u32 smem_u32(const void* p) {
    u32 a;
    asm("{ .reg .u64 t; cvta.to.shared.u64 t, %1; cvt.u32.u64 %0, t; }" : "=r"(a) : "l"(p));
    return a;
}

#define SWZ(o) ((o) ^ (((o) >> 3) & 0x70))

#define CP_ASYNC16(saddr, gptr) \
    asm volatile("cp.async.ca.shared.global [%0], [%1], 16;" :: "r"(saddr), "l"(gptr) : "memory")
#define CP_COMMIT() asm volatile("cp.async.commit_group;" ::: "memory")
#define CP_WAIT3()  asm volatile("cp.async.wait_group 3;" ::: "memory")
#define CP_WAIT0()  asm volatile("cp.async.wait_group 0;" ::: "memory")

#define LDMX4(r0, r1, r2, r3, addr) \
    asm volatile("ldmatrix.sync.aligned.m8n8.x4.shared.b16 {%0,%1,%2,%3}, [%4];" \
        : "=r"(r0), "=r"(r1), "=r"(r2), "=r"(r3) : "r"(addr))

#define MMAF16(d0, d1, d2, d3, a0, a1, a2, a3, b0, b1) \
    asm volatile("mma.sync.aligned.m16n8k16.row.col.f32.f16.f16.f32 " \
        "{%0,%1,%2,%3}, {%4,%5,%6,%7}, {%8,%9}, {%0,%1,%2,%3};" \
        : "+f"(d0), "+f"(d1), "+f"(d2), "+f"(d3) \
        : "r"(a0), "r"(a1), "r"(a2), "r"(a3), "r"(b0), "r"(b1))

// ---------------- scratch ----------------
__device__ float g_qkvp[(size_t)NB*NS*NQKV];    // fused qkv projection out
__device__ float g_Q  [(size_t)NB*NH*NS*ND];
__device__ float g_K  [(size_t)NB*NKV*NS*ND];
__device__ float g_V  [(size_t)NB*NKV*NS*ND];
__device__ float g_bs [(size_t)NB*NKV*(NS/64)*ND];
__device__ float g_att[(size_t)NB*NS*NH*ND];

__device__ __half g_ah[(size_t)NB*NS*NHID], g_al[(size_t)NB*NS*NHID];     // hs split
__device__ __half g_wqkv[(size_t)NQKV*NHID];                              // fused weights
__device__ __half g_wo[(size_t)NHID*NHID];
__device__ __half g_oh[(size_t)NB*NS*NHID], g_ol[(size_t)NB*NS*NHID];     // att split

// ---------------- fp32 -> fp16 hi/lo split ----------------
__global__ __launch_bounds__(256) void cvt_split_h(
    const float* __restrict__ x, __half* __restrict__ hi,
    __half* __restrict__ lo, int n4)
{
    int i = blockIdx.x * 256 + threadIdx.x;
    if (i >= n4) return;
    float4 v = *(const float4*)(x + (size_t)i * 4);
    __half h0 = __float2half(v.x), h1 = __float2half(v.y);
    __half h2 = __float2half(v.z), h3 = __float2half(v.w);
    __half l0 = __float2half(v.x - __half2float(h0));
    __half l1 = __float2half(v.y - __half2float(h1));
    __half l2 = __float2half(v.z - __half2float(h2));
    __half l3 = __float2half(v.w - __half2float(h3));
    ushort4 H, L;
    H.x = __half_as_ushort(h0); H.y = __half_as_ushort(h1);
    H.z = __half_as_ushort(h2); H.w = __half_as_ushort(h3);
    L.x = __half_as_ushort(l0); L.y = __half_as_ushort(l1);
    L.z = __half_as_ushort(l2); L.w = __half_as_ushort(l3);
    *(ushort4*)(hi + (size_t)i * 4) = H;
    *(ushort4*)(lo + (size_t)i * 4) = L;
}

// ---------------- fp32 -> fp16 (weights) ----------------
__global__ __launch_bounds__(256) void cvt_h(
    const float* __restrict__ x, __half* __restrict__ y, int n4)
{
    int i = blockIdx.x * 256 + threadIdx.x;
    if (i >= n4) return;
    float4 v = *(const float4*)(x + (size_t)i * 4);
    ushort4 H;
    H.x = __half_as_ushort(__float2half(v.x));
    H.y = __half_as_ushort(__float2half(v.y));
    H.z = __half_as_ushort(__float2half(v.z));
    H.w = __half_as_ushort(__float2half(v.w));
    *(ushort4*)(y + (size_t)i * 4) = H;
}

// ---------------- HMMA fp16 split-A GEMM ----------------
// C[m,n] = sum_k A[m,k]*B[n,k]  via Ah*B + Al*B
// block tile 128x128, 8 warps (warptile 64x32), K-chunk 64, 4-stage cp.async
#define GS_STAGE 49152
#define GS_AH 0
#define GS_AL 16384
#define GS_B  32768
#define GS_TOTAL (4 * GS_STAGE)

__global__ __launch_bounds__(256, 1) void gemm_mma(
    const __half* __restrict__ Ah, const __half* __restrict__ Al,
    const __half* __restrict__ B,
    float* __restrict__ C, int M, int N, int K)
{
    extern __shared__ char sm[];
    u32 sb = smem_u32(sm);
    int tid = threadIdx.x;
    int lane = tid & 31, wid = tid >> 5;
    int warpM = wid >> 2, warpN = wid & 3;
    int bm = blockIdx.y * 128, bn = blockIdx.x * 128;

    const int nIt = K >> 6;   // 32

    float d[4][4][4];
#pragma unroll
    for (int i = 0; i < 4; i++)
#pragma unroll
        for (int j = 0; j < 4; j++)
#pragma unroll
            for (int c = 0; c < 4; c++) d[i][j][c] = 0.f;

    int lrow = tid >> 3, lcb = tid & 7;      // 32 rows per pass, 4 passes
    u32 ldo = SWZ((u32)(lrow * 128 + lcb * 16));
    size_t gA = (size_t)(bm + lrow) * K + lcb * 8;
    size_t gB = (size_t)(bn + lrow) * K + lcb * 8;

    // prologue: stages 0,1,2
#pragma unroll
    for (int pit = 0; pit < 3; pit++) {
        u32 stg = sb + pit * GS_STAGE;
        int k0 = pit << 6;
#pragma unroll
        for (int i = 0; i < 4; i++) {
            u32 doff = ldo + (u32)(i * 32 * 128);
            size_t ga = gA + (size_t)(i * 32) * K + k0;
            size_t gb = gB + (size_t)(i * 32) * K + k0;
            CP_ASYNC16(stg + GS_AH + doff, Ah + ga);
            CP_ASYNC16(stg + GS_AL + doff, Al + ga);
            CP_ASYNC16(stg + GS_B  + doff, B  + gb);
        }
        CP_COMMIT();
    }

    // precompute ldmatrix offsets (swizzled) for kk=0..3
    u32 a_off[4][4], b_off[2][4];
#pragma unroll
    for (int kk = 0; kk < 4; kk++) {
        u32 colb = kk * 32 + ((lane >> 4) << 4);
#pragma unroll
        for (int i = 0; i < 4; i++) {
            int row = warpM * 64 + i * 16 + (lane & 15);
            a_off[i][kk] = SWZ((u32)(row * 128 + colb));
        }
        u32 colb2 = kk * 32 + (((lane >> 3) & 1) << 4);
#pragma unroll
        for (int p = 0; p < 2; p++) {
            int row = warpN * 32 + p * 16 + (lane & 7) + ((lane >> 4) << 3);
            b_off[p][kk] = SWZ((u32)(row * 128 + colb2));
        }
    }

    for (int it = 0; it < nIt; it++) {
        __syncthreads();
        if (it + 3 < nIt) {
            u32 stg = sb + ((it + 3) & 3) * GS_STAGE;
            int k0 = (it + 3) << 6;
#pragma unroll
            for (int i = 0; i < 4; i++) {
                u32 doff = ldo + (u32)(i * 32 * 128);
                size_t ga = gA + (size_t)(i * 32) * K + k0;
                size_t gb = gB + (size_t)(i * 32) * K + k0;
                CP_ASYNC16(stg + GS_AH + doff, Ah + ga);
                CP_ASYNC16(stg + GS_AL + doff, Al + ga);
                CP_ASYNC16(stg + GS_B  + doff, B  + gb);
            }
        }
        CP_COMMIT();
        CP_WAIT3();
        __syncthreads();

        u32 stg = sb + (it & 3) * GS_STAGE;
#pragma unroll
        for (int kk = 0; kk < 4; kk++) {
            u32 ah[4][4], al[4][4];
#pragma unroll
            for (int i = 0; i < 4; i++) {
                LDMX4(ah[i][0], ah[i][1], ah[i][2], ah[i][3], stg + GS_AH + a_off[i][kk]);
                LDMX4(al[i][0], al[i][1], al[i][2], al[i][3], stg + GS_AL + a_off[i][kk]);
            }
            u32 bb[2][4];
#pragma unroll
            for (int p = 0; p < 2; p++)
                LDMX4(bb[p][0], bb[p][1], bb[p][2], bb[p][3], stg + GS_B + b_off[p][kk]);
#pragma unroll
            for (int i = 0; i < 4; i++) {
#pragma unroll
                for (int j = 0; j < 4; j++) {
                    int p = j >> 1, h2 = (j & 1) << 1;
                    MMAF16(d[i][j][0], d[i][j][1], d[i][j][2], d[i][j][3],
                           ah[i][0], ah[i][1], ah[i][2], ah[i][3],
                           bb[p][h2], bb[p][h2 + 1]);
                    MMAF16(d[i][j][0], d[i][j][1], d[i][j][2], d[i][j][3],
                           al[i][0], al[i][1], al[i][2], al[i][3],
                           bb[p][h2], bb[p][h2 + 1]);
                }
            }
        }
    }
    CP_WAIT0();

    // epilogue
#pragma unroll
    for (int i = 0; i < 4; i++) {
#pragma unroll
        for (int j = 0; j < 4; j++) {
            int r0 = bm + warpM * 64 + i * 16 + (lane >> 2);
            int cc = bn + warpN * 32 + j * 8 + (lane & 3) * 2;
            float2 v0 = make_float2(d[i][j][0], d[i][j][1]);
            float2 v1 = make_float2(d[i][j][2], d[i][j][3]);
            *(float2*)(C + (size_t)r0 * N + cc) = v0;
            *(float2*)(C + (size_t)(r0 + 8) * N + cc) = v1;
        }
    }
}

// ---------------- fused RoPE + unit-LayerNorm (+ q scale) ----------------
// reads fused qkvp rows [3072]: q 0..2047, k 2048..2559, v 2560..3071
__global__ __launch_bounds__(256) void rope_ln_kernel(
    const float* __restrict__ qkvp,
    float* __restrict__ Qo, float* __restrict__ Ko, float* __restrict__ Vo)
{
    __shared__ float sh[ND];
    __shared__ float redA[8], redB[8];
    __shared__ float s_mu, s_inv;
    int bs = blockIdx.x;
    int s  = bs & (NS - 1);
    int b  = bs >> 11;
    int u  = blockIdx.y;
    int d  = threadIdx.x;

    const float* src; float* dst; bool doRope; float scale;
    if (u < NH) {
        src = qkvp + (size_t)bs * NQKV + u * ND;
        dst = Qo + (((size_t)(b * NH + u) * NS) + s) * ND;
        doRope = true; scale = 16.0f;
    } else if (u < NH + NKV) {
        int h = u - NH;
        src = qkvp + (size_t)bs * NQKV + 2048 + h * ND;
        dst = Ko + (((size_t)(b * NKV + h) * NS) + s) * ND;
        doRope = true; scale = 1.0f;
    } else {
        int h = u - NH - NKV;
        src = qkvp + (size_t)bs * NQKV + 2560 + h * ND;
        dst = Vo + (((size_t)(b * NKV + h) * NS) + s) * ND;
        doRope = false; scale = 1.0f;
    }

    float x = src[d];
    float r = x;
    if (doRope) {
        sh[d] = x;
        __syncthreads();
        int j = d & 127;
        // 1/theta^(j/128) = 2^(-j*log2(1e6)/128)
        float invf = exp2f(-(float)j * 0.15571537945f);
        float ang = (float)s * invf;
        float c, sn;
        __sincosf(ang, &sn, &c);
        // use precise sin/cos (sincosf) to match reference closely
        sn = sinf(ang); c = cosf(ang);
        float partner = (d < 128) ? -sh[d + 128] : sh[d - 128];
        r = x * c + partner * sn;
    }
    float s1 = r, s2 = r * r;
#pragma unroll
    for (int off = 16; off; off >>= 1) {
        s1 += __shfl_xor_sync(~0u, s1, off);
        s2 += __shfl_xor_sync(~0u, s2, off);
    }
    int w = d >> 5;
    if ((d & 31) == 0) { redA[w] = s1; redB[w] = s2; }
    __syncthreads();
    if (d == 0) {
        float A = 0.f, Bv = 0.f;
#pragma unroll
        for (int i = 0; i < 8; i++) { A += redA[i]; Bv += redB[i]; }
        float mu  = A * (1.0f / 256.0f);
        float var = Bv * (1.0f / 256.0f) - mu * mu;
        s_mu = mu; s_inv = rsqrtf(var + 1e-6f);
    }
    __syncthreads();
    dst[d] = (r - s_mu) * s_inv * scale;
}

// ---------------- 64-row block sums of V (mask-correction) ----------------
__global__ __launch_bounds__(256) void vblocksum_kernel(
    const float* __restrict__ V, float* __restrict__ BSo)
{
    int bh = blockIdx.x, blk = blockIdx.y, d = threadIdx.x;
    const float* v = V + ((size_t)bh * NS + blk * 64) * ND + d;
    float s = 0.f;
#pragma unroll 8
    for (int i = 0; i < 64; i++) s += v[(size_t)i * ND];
    BSo[((size_t)bh * (NS / 64) + blk) * ND + d] = s;
}

// ---------------- sliding-window softcapped flash attention ----------------
#define AT_BM 64
#define AT_BN 64
#define QS_STR 260
#define KT_STR 68
#define VS_STR 260
#define PS_STR 68
#define ATT_SMEM ((16640 + 17408 + 16640 + 4352 + 256) * 4)

__global__ __launch_bounds__(256, 1) void attn_kernel(
    const float* __restrict__ Q, const float* __restrict__ K,
    const float* __restrict__ V, const float* __restrict__ BS,
    float* __restrict__ O)
{
    extern __shared__ __align__(16) float smf[];
    float* Qs    = smf;
    float* Kt    = smf + 16640;
    float* Vs    = smf + 34048;
    float* Ps    = smf + 50688;
    float* corrv = smf + 55040;

    int tid = threadIdx.x;
    int tx = tid & 15, ty = tid >> 4;
    int qt = blockIdx.x, h = blockIdx.y, b = blockIdx.z;
    int qs = qt * AT_BM;
    int kvh = h >> 2;

    const float* Qb = Q + (((size_t)(b * NH  + h  ) * NS) + qs) * ND;
    const float* Kb = K + ((size_t)(b * NKV + kvh) * NS) * ND;
    const float* Vb = V + ((size_t)(b * NKV + kvh) * NS) * ND;
    const float* Bb = BS + (size_t)(b * NKV + kvh) * (NS / 64) * ND;

    int t0 = qs - (NSW - 1);
    int kstart = (t0 <= 0) ? 0 : (t0 & ~63);
    int kend = qs + AT_BM;
    float Ncf = (float)(NS - (kend - kstart));
    int bs0 = kstart >> 6, bs1 = kend >> 6;

    {
        float c = 0.f;
#pragma unroll
        for (int blk = 0; blk < NS / 64; blk++) {
            float x = Bb[(size_t)blk * ND + tid];
            if (blk < bs0 || blk >= bs1) c += x;
        }
        corrv[tid] = c;
    }
#pragma unroll
    for (int it = 0; it < 16; it++) {
        int idx = tid + it * 256;
        int row = idx >> 6, c4 = idx & 63;
        float4 qv = *(const float4*)(Qb + (size_t)row * ND + (c4 << 2));
        float* q = Qs + row * QS_STR + (c4 << 2);
        q[0] = qv.x; q[1] = qv.y; q[2] = qv.z; q[3] = qv.w;
    }

    float2 acc[4][8];
#pragma unroll
    for (int i = 0; i < 4; i++)
#pragma unroll
        for (int c = 0; c < 8; c++) acc[i][c] = make_float2(0.f, 0.f);
    float Mrow[4], Lrow[4];
#pragma unroll
    for (int i = 0; i < 4; i++) { Mrow[i] = -3.0e38f; Lrow[i] = 0.f; }

    for (int k0 = kstart; k0 < kend; k0 += AT_BN) {
        __syncthreads();
#pragma unroll
        for (int it = 0; it < 16; it++) {
            int idx = tid + it * 256;
            int row = idx >> 6, c4 = idx & 63;
            float4 kv = *(const float4*)(Kb + (size_t)(k0 + row) * ND + (c4 << 2));
            Kt[(c4 * 4 + 0) * KT_STR + row] = kv.x;
            Kt[(c4 * 4 + 1) * KT_STR + row] = kv.y;
            Kt[(c4 * 4 + 2) * KT_STR + row] = kv.z;
            Kt[(c4 * 4 + 3) * KT_STR + row] = kv.w;
            float4 vv = *(const float4*)(Vb + (size_t)(k0 + row) * ND + (c4 << 2));
            *(float4*)(Vs + row * VS_STR + (c4 << 2)) = vv;
        }
        __syncthreads();

        float2 s2[4][2];
#pragma unroll
        for (int i = 0; i < 4; i++) { s2[i][0] = make_float2(0.f,0.f); s2[i][1] = make_float2(0.f,0.f); }
        const float* qrow = Qs + (ty << 2) * QS_STR;
#pragma unroll 8
        for (int d = 0; d < ND; d++) {
            float4 kq  = *(const float4*)(Kt + d * KT_STR + (tx << 2));
            float2 b01 = make_float2(kq.x, kq.y);
            float2 b23 = make_float2(kq.z, kq.w);
#pragma unroll
            for (int ii = 0; ii < 4; ii++) {
                float a = qrow[ii * QS_STR + d];
                float2 ap = make_float2(a, a);
                s2[ii][0] = ffma2(s2[ii][0], ap, b01);
                s2[ii][1] = ffma2(s2[ii][1], ap, b23);
            }
        }

#pragma unroll
        for (int ii = 0; ii < 4; ii++) {
            int gi = qs + (ty << 2) + ii;
            float sc[4] = { s2[ii][0].x, s2[ii][0].y, s2[ii][1].x, s2[ii][1].y };
            float rmax = -1e30f;
#pragma unroll
            for (int jj = 0; jj < 4; jj++) {
                int gj = k0 + (tx << 2) + jj;
                float v;
                if (gj <= gi && gj > gi - NSW)
                    v = 30.0f * tanhf(sc[jj] * (1.0f / 30.0f));
                else
                    v = -30.0f;
                sc[jj] = v;
                rmax = fmaxf(rmax, v);
            }
#pragma unroll
            for (int off = 8; off; off >>= 1) rmax = fmaxf(rmax, __shfl_xor_sync(~0u, rmax, off));
            float Mnew = fmaxf(Mrow[ii], rmax);
            float f = expf(Mrow[ii] - Mnew);
            Mrow[ii] = Mnew;
            float rs = 0.f;
#pragma unroll
            for (int jj = 0; jj < 4; jj++) {
                float p = expf(sc[jj] - Mnew);
                Ps[((ty << 2) + ii) * PS_STR + (tx << 2) + jj] = p;
                rs += p;
            }
#pragma unroll
            for (int off = 8; off; off >>= 1) rs += __shfl_xor_sync(~0u, rs, off);
            Lrow[ii] = Lrow[ii] * f + rs;
#pragma unroll
            for (int cc = 0; cc < 8; cc++) { acc[ii][cc].x *= f; acc[ii][cc].y *= f; }
        }
        __syncthreads();

#pragma unroll 4
        for (int kk = 0; kk < AT_BN; kk++) {
            const float* vrow = Vs + kk * VS_STR + (tx << 4);
            float4 v0 = *(const float4*)(vrow);
            float4 v1 = *(const float4*)(vrow + 4);
            float4 v2 = *(const float4*)(vrow + 8);
            float4 v3 = *(const float4*)(vrow + 12);
            float2 vv[8] = {
                make_float2(v0.x,v0.y), make_float2(v0.z,v0.w),
                make_float2(v1.x,v1.y), make_float2(v1.z,v1.w),
                make_float2(v2.x,v2.y), make_float2(v2.z,v2.w),
                make_float2(v3.x,v3.y), make_float2(v3.z,v3.w)
            };
#pragma unroll
            for (int ii = 0; ii < 4; ii++) {
                float p = Ps[((ty << 2) + ii) * PS_STR + kk];
                float2 pp = make_float2(p, p);
#pragma unroll
                for (int cc = 0; cc < 8; cc++) acc[ii][cc] = ffma2(acc[ii][cc], pp, vv[cc]);
            }
        }
    }

#pragma unroll
    for (int ii = 0; ii < 4; ii++) {
        float ce = expf(-30.0f - Mrow[ii]);
        float invL = 1.0f / (Lrow[ii] + ce * Ncf);
        int row = qs + (ty << 2) + ii;
        float* ob = O + (((size_t)(b * NS + row) * NH) + h) * ND + (tx << 4);
#pragma unroll
        for (int g = 0; g < 4; g++) {
            float2 a0 = acc[ii][g * 2], a1 = acc[ii][g * 2 + 1];
            int c0 = (tx << 4) + g * 4;
            float4 o;
            o.x = (a0.x + ce * corrv[c0 + 0]) * invL;
            o.y = (a0.y + ce * corrv[c0 + 1]) * invL;
            o.z = (a1.x + ce * corrv[c0 + 2]) * invL;
            o.w = (a1.y + ce * corrv[c0 + 3]) * invL;
            *(float4*)(ob + g * 4) = o;
        }
    }
}

// ---------------- launch ----------------
extern "C" void kernel_launch(void* const* d_in, const int* in_sizes, int n_in,
                              void* d_out, int out_size)
{
    const float* hs = (const float*)d_in[0];
    const float* Wq = (const float*)d_in[1];
    const float* Wk = (const float*)d_in[2];
    const float* Wv = (const float*)d_in[3];
    const float* Wo = (const float*)d_in[4];
    float* out = (float*)d_out;

    float *qkvp, *Qn, *Kn, *Vn, *bs, *att;
    cudaGetSymbolAddress((void**)&qkvp, g_qkvp);
    cudaGetSymbolAddress((void**)&Qn,  g_Q);
    cudaGetSymbolAddress((void**)&Kn,  g_K);
    cudaGetSymbolAddress((void**)&Vn,  g_V);
    cudaGetSymbolAddress((void**)&bs,  g_bs);
    cudaGetSymbolAddress((void**)&att, g_att);

    __half *ah,*al,*wqkv,*wo,*oh,*ol;
    cudaGetSymbolAddress((void**)&ah, g_ah); cudaGetSymbolAddress((void**)&al, g_al);
    cudaGetSymbolAddress((void**)&wqkv, g_wqkv);
    cudaGetSymbolAddress((void**)&wo, g_wo);
    cudaGetSymbolAddress((void**)&oh, g_oh); cudaGetSymbolAddress((void**)&ol, g_ol);

    const int M = NB * NS;   // 4096

    cudaFuncSetAttribute(gemm_mma, cudaFuncAttributeMaxDynamicSharedMemorySize, GS_TOTAL);
    cudaFuncSetAttribute(attn_kernel, cudaFuncAttributeMaxDynamicSharedMemorySize, ATT_SMEM);

    // conversions: hs split; weights single fp16 (QKV packed into one buffer)
    {
        int n;
        n = M * NHID;        cvt_split_h<<<n/1024, 256>>>(hs, ah, al, n/4);
        n = NH * ND * NHID;  cvt_h<<<n/1024, 256>>>(Wq, wqkv, n/4);
        n = NKV * ND * NHID; cvt_h<<<n/1024, 256>>>(Wk, wqkv + (size_t)2048*NHID, n/4);
        n = NKV * ND * NHID; cvt_h<<<n/1024, 256>>>(Wv, wqkv + (size_t)2560*NHID, n/4);
        n = NHID * NHID;     cvt_h<<<n/1024, 256>>>(Wo, wo, n/4);
    }

    // fused QKV projection (one GEMM, N=3072)
    gemm_mma<<<dim3(NQKV/128, M/128), 256, GS_TOTAL>>>(ah, al, wqkv, qkvp, M, NQKV, NHID);

    // rope + per-head layernorm (+ query scaling folded)
    rope_ln_kernel<<<dim3(NB * NS, NH + 2 * NKV), 256>>>(qkvp, Qn, Kn, Vn);

    // 64-row block sums of normalized V (exact masked-softmax correction)
    vblocksum_kernel<<<dim3(NB * NKV, NS / 64), 256>>>(Vn, bs);

    // attention
    attn_kernel<<<dim3(NS / AT_BM, NH, NB), 256, ATT_SMEM>>>(Qn, Kn, Vn, bs, att);

    // output projection
    {
        int n = M * NHID;
        cvt_split_h<<<n/1024, 256>>>(att, oh, ol, n/4);
    }
    gemm_mma<<<dim3(NHID/128, M/128), 256, GS_TOTAL>>>(oh, ol, wo, out, M, NHID, NHID);
}